// round 12
// baseline (speedup 1.0000x reference)
#include <cuda_runtime.h>
#include <cuda_bf16.h>
#include <cstdint>

// ---------------------------------------------------------------------------
// RnnTfModel: k_embproj (exact R1) + fused LSTM/head.
// R12 = R11 resubmit (infra failure) + fixed smem zero-init OOB.
//   In-warp shfl transpose-reduce combine (lane = (unit, k-quarter)),
//   c-state in registers, 2 barriers/step, double-buffered h1/h2.
// B=512, T=1024, D=H=64, 4H=256, V=8193. 128 blocks x 256 threads.
// ---------------------------------------------------------------------------

#define B_   512
#define T_   1024
#define D_   64
#define G4_  256
#define V_   8193
#define NB_  4
#define NBLK_ 128
#define THR_ 256

using ull = unsigned long long;

__device__ float g_table[V_ * G4_];      // projected embedding table (8.4 MB)

__device__ __forceinline__ void ffma2(ull& d, ull a, ull b) {
    asm("fma.rn.f32x2 %0, %1, %2, %0;" : "+l"(d) : "l"(a), "l"(b));
}
__device__ __forceinline__ float2 unpack2(ull v) {
    float2 f;
    asm("mov.b64 {%0, %1}, %2;" : "=f"(f.x), "=f"(f.y) : "l"(v));
    return f;
}
__device__ __forceinline__ ull pack2(float lo, float hi) {
    ull v;
    asm("mov.b64 %0, {%1, %2};" : "=l"(v) : "f"(lo), "f"(hi));
    return v;
}
__device__ __forceinline__ float sigm_(float x) {
    return 1.0f / (1.0f + __expf(-x));
}
__device__ __forceinline__ float tanh_(float x) {
    float e = __expf(-2.0f * x);
    return (1.0f - e) / (1.0f + e);
}
__device__ __forceinline__ float shflx(float v, int m) {
    return __shfl_xor_sync(0xffffffffu, v, m);
}

// ---------------------------------------------------------------------------
// Kernel 1: projected embedding table — EXACT R1 code.
// ---------------------------------------------------------------------------
__global__ void k_embproj(const float* __restrict__ emb,
                          const float* __restrict__ W1,
                          const float* __restrict__ b1) {
    int v = blockIdx.x;
    int j = threadIdx.x;
    __shared__ float e[D_];
    if (j < D_) e[j] = emb[v * D_ + j];
    __syncthreads();
    float acc = b1[j];
#pragma unroll
    for (int k = 0; k < D_; k++) acc += e[k] * __ldg(&W1[k * G4_ + j]);
    g_table[v * G4_ + j] = acc;
}

// ---------------------------------------------------------------------------
// 4-lane transpose-reduce: input s[r][c] = this lane's k-quarter partial for
// row r, gate c. Output z[c] = full k-sum for row (kq), gate c.
// Lanes within a quad (lane bits 0-1 = kq) exchange so each ends with its row.
// ---------------------------------------------------------------------------
__device__ __forceinline__ void quad_reduce(const float s[4][4], float z[4],
                                            int kq) {
    const bool p1 = (kq & 1), p2 = ((kq >> 1) & 1);
    float t0[4], t1[4];
#pragma unroll
    for (int c = 0; c < 4; c++) {
        float a0 = s[0][c] + shflx(s[0][c], 1);
        float a1 = s[1][c] + shflx(s[1][c], 1);
        float a2 = s[2][c] + shflx(s[2][c], 1);
        float a3 = s[3][c] + shflx(s[3][c], 1);
        t0[c] = p1 ? a1 : a0;
        t1[c] = p1 ? a3 : a2;
    }
#pragma unroll
    for (int c = 0; c < 4; c++) {
        float b0 = t0[c] + shflx(t0[c], 2);
        float b1 = t1[c] + shflx(t1[c], 2);
        z[c] = p2 ? b1 : b0;
    }
}

// ---------------------------------------------------------------------------
// Kernel 2: fused LSTM + head.
// lane = (u, kq): kq = lane&3 (k-quarter AND state row), u = warp*8+(lane>>2).
// Thread computes 4 gates x 4 rows over its k-quarter; in-warp reduce; owns
// c1,c2 for (row=kq, unit=u) in registers.
// ---------------------------------------------------------------------------
__global__ void __launch_bounds__(THR_, 1)
k_main(const int* __restrict__ code_in,
       const float* __restrict__ U1,
       const float* __restrict__ W2,
       const float* __restrict__ U2,
       const float* __restrict__ b2,
       const float* __restrict__ aux,
       const float* __restrict__ Wlm, const float* __restrict__ blm,
       const float* __restrict__ gamma, const float* __restrict__ beta,
       const float* __restrict__ mean, const float* __restrict__ var,
       const float* __restrict__ W3, const float* __restrict__ b3,
       const float* __restrict__ W4, const float* __restrict__ b4,
       float* __restrict__ out) {
    __shared__ __align__(16) float hc1[2][NB_][D_];   // h1 double buffer
    __shared__ __align__(16) float hc2[2][NB_][D_];   // h2 double buffer
    __shared__ __align__(16) int code_s[NB_ * T_];
    __shared__ float zbn[NB_][66];
    __shared__ float hid[NB_][32];

    const int j    = threadIdx.x;
    const int lane = j & 31;
    const int warp = j >> 5;
    const int kq   = lane & 3;               // k-quarter == state row
    const int u    = warp * 8 + (lane >> 2); // hidden unit
    const int b0   = blockIdx.x * NB_;

    // ---- layer-1 weights: U1 rows [16kq,16kq+16) x gate cols u+64c ----
    ull wA[4][8];
#pragma unroll
    for (int c = 0; c < 4; c++)
#pragma unroll
        for (int p = 0; p < 8; p++) {
            int k = 16 * kq + 2 * p;
            wA[c][p] = pack2(__ldg(&U1[k * G4_ + u + 64 * c]),
                             __ldg(&U1[(k + 1) * G4_ + u + 64 * c]));
        }
    // ---- layer-2 weights: stacked [W2;U2] rows [32kq,32kq+32) ----
    const float* M2 = (kq < 2) ? W2 : U2;
    const int kr0 = 32 * (kq & 1);
    ull wB[4][16];
#pragma unroll
    for (int c = 0; c < 4; c++)
#pragma unroll
        for (int p = 0; p < 16; p++) {
            int k = kr0 + 2 * p;
            wB[c][p] = pack2(__ldg(&M2[k * G4_ + u + 64 * c]),
                             __ldg(&M2[(k + 1) * G4_ + u + 64 * c]));
        }
    float4 b2c;
    b2c.x = __ldg(&b2[u]);
    b2c.y = __ldg(&b2[64 + u]);
    b2c.z = __ldg(&b2[128 + u]);
    b2c.w = __ldg(&b2[192 + u]);

    for (int i = j; i < NB_ * T_; i += THR_) {
        int r = i >> 10, t = i & (T_ - 1);
        code_s[i] = code_in[(b0 + r) * T_ + t];
    }
    // zero both h double-buffers: 2*512 floats, 256 threads x 4 stores
    ((float*)hc1)[j]       = 0.0f;
    ((float*)hc1)[j + 256] = 0.0f;
    ((float*)hc2)[j]       = 0.0f;
    ((float*)hc2)[j + 256] = 0.0f;
    __syncthreads();

    float c1 = 0.0f, c2 = 0.0f;

    // xz prefetch for t=0 (this lane's row is kq)
    float4 cur;
    {
        const float* row = &g_table[(size_t)code_s[kq * T_] * G4_];
        cur.x = __ldg(&row[u]);
        cur.y = __ldg(&row[64 + u]);
        cur.z = __ldg(&row[128 + u]);
        cur.w = __ldg(&row[192 + u]);
    }

    // ============================ LSTM loop ================================
    for (int t = 0; t < T_; t++) {
        const int cb = t & 1;          // buffer written this step
        const int pv = (t + 1) & 1;    // buffer holding state of t-1

        float4 nxt;
        {
            int tn = (t + 1 < T_) ? (t + 1) : (T_ - 1);
            const float* row = &g_table[(size_t)code_s[kq * T_ + tn] * G4_];
            nxt.x = __ldg(&row[u]);
            nxt.y = __ldg(&row[64 + u]);
            nxt.z = __ldg(&row[128 + u]);
            nxt.w = __ldg(&row[192 + u]);
        }

        // ---- phase A: z1 partials over k-quarter of h1_{t-1} ----
        {
            ull acc[4][4] = {{0,0,0,0},{0,0,0,0},{0,0,0,0},{0,0,0,0}};
#pragma unroll
            for (int r = 0; r < 4; r++) {
#pragma unroll
                for (int i = 0; i < 4; i++) {
                    ulonglong2 hv = *(const ulonglong2*)
                        &hc1[pv][r][16 * kq + 4 * i];
#pragma unroll
                    for (int c = 0; c < 4; c++) {
                        ffma2(acc[r][c], hv.x, wA[c][2 * i]);
                        ffma2(acc[r][c], hv.y, wA[c][2 * i + 1]);
                    }
                }
            }
            float s[4][4];
#pragma unroll
            for (int r = 0; r < 4; r++)
#pragma unroll
                for (int c = 0; c < 4; c++) {
                    float2 p = unpack2(acc[r][c]);
                    s[r][c] = p.x + p.y;
                }
            float z[4];
            quad_reduce(s, z, kq);
            // combine: this lane owns (row=kq, unit=u)
            float iv = sigm_(z[0] + cur.x);
            float fv = sigm_(z[1] + cur.y);
            float gv = tanh_(z[2] + cur.z);
            float ov = sigm_(z[3] + cur.w);
            c1 = fv * c1 + iv * gv;
            hc1[cb][kq][u] = ov * tanh_(c1);     // h1_t
        }
        __syncthreads();   // S1: h1_t visible

        // ---- phase B: z2 partials over k-quarter of [h1_t ; h2_{t-1}] ----
        {
            const float* kb = (kq < 2) ? &hc1[cb][0][0] : &hc2[pv][0][0];
            const int off = 32 * (kq & 1);
            ull acc[4][4] = {{0,0,0,0},{0,0,0,0},{0,0,0,0},{0,0,0,0}};
#pragma unroll
            for (int r = 0; r < 4; r++) {
#pragma unroll
                for (int i = 0; i < 8; i++) {
                    ulonglong2 hv = *(const ulonglong2*)
                        &kb[r * D_ + off + 4 * i];
#pragma unroll
                    for (int c = 0; c < 4; c++) {
                        ffma2(acc[r][c], hv.x, wB[c][2 * i]);
                        ffma2(acc[r][c], hv.y, wB[c][2 * i + 1]);
                    }
                }
            }
            float s[4][4];
#pragma unroll
            for (int r = 0; r < 4; r++)
#pragma unroll
                for (int c = 0; c < 4; c++) {
                    float2 p = unpack2(acc[r][c]);
                    s[r][c] = p.x + p.y;
                }
            float z[4];
            quad_reduce(s, z, kq);
            float iv = sigm_(z[0] + b2c.x);
            float fv = sigm_(z[1] + b2c.y);
            float gv = tanh_(z[2] + b2c.z);
            float ov = sigm_(z[3] + b2c.w);
            c2 = fv * c2 + iv * gv;
            hc2[cb][kq][u] = ov * tanh_(c2);     // h2_t
        }
        __syncthreads();   // S2: h2_t visible; all reads of old buffers done

        cur = nxt;
    }

    // final h2 lives in hc2[(T_-1)&1] = hc2[1]
    // ============================ head (4 rows) ============================
    if (j < 264) {
        int r = j / 66, k = j % 66;
        float v = (k < 2) ? aux[(b0 + r) * 2 + k] : hc2[1][r][k - 2];
        zbn[r][k] =
            gamma[k] * (v - mean[k]) * rsqrtf(var[k] + 1e-3f) + beta[k];
    }
    __syncthreads();
    if (j < 128) {
        int r = j >> 5, i = j & 31;
        float acc = b3[i];
#pragma unroll
        for (int k = 0; k < 66; k++)
            acc += zbn[r][k] * __ldg(&W3[k * 32 + i]);
        hid[r][i] = fmaxf(acc, 0.0f);
    }
    __syncthreads();
    if (j < NB_) {
        int r = j;
        float o0 = b4[0], o1 = b4[1];
#pragma unroll
        for (int k = 0; k < 32; k++) {
            o0 += hid[r][k] * __ldg(&W4[k * 2 + 0]);
            o1 += hid[r][k] * __ldg(&W4[k * 2 + 1]);
        }
        float m = fmaxf(o0, o1);
        float e0 = __expf(o0 - m), e1 = __expf(o1 - m);
        float inv = 1.0f / (e0 + e1);
        out[(b0 + r) * 2 + 0] = e0 * inv;
        out[(b0 + r) * 2 + 1] = e1 * inv;

        float l0 = blm[0], l1 = blm[1];
#pragma unroll
        for (int k = 0; k < 64; k++) {
            float h = hc2[1][r][k];
            l0 += h * __ldg(&Wlm[k * 2 + 0]);
            l1 += h * __ldg(&Wlm[k * 2 + 1]);
        }
        out[B_ * 2 + (b0 + r) * 2 + 0] = sigm_(l0);
        out[B_ * 2 + (b0 + r) * 2 + 1] = sigm_(l1);
    }
}

// ---------------------------------------------------------------------------
// launcher
// inputs: 0 aux_in, 1 code_in, 2 emb, 3 W1, 4 U1, 5 b1, 6 W2, 7 U2, 8 b2,
//         9 Wlm, 10 blm, 11 bn_gamma, 12 bn_beta, 13 bn_mean, 14 bn_var,
//         15 W3, 16 b3, 17 W4, 18 b4
// ---------------------------------------------------------------------------
extern "C" void kernel_launch(void* const* d_in, const int* in_sizes, int n_in,
                              void* d_out, int out_size) {
    const float* aux   = (const float*)d_in[0];
    const int*   code  = (const int*)d_in[1];
    const float* emb   = (const float*)d_in[2];
    const float* W1    = (const float*)d_in[3];
    const float* U1    = (const float*)d_in[4];
    const float* b1    = (const float*)d_in[5];
    const float* W2    = (const float*)d_in[6];
    const float* U2    = (const float*)d_in[7];
    const float* b2    = (const float*)d_in[8];
    const float* Wlm   = (const float*)d_in[9];
    const float* blm   = (const float*)d_in[10];
    const float* gamma = (const float*)d_in[11];
    const float* beta  = (const float*)d_in[12];
    const float* mean  = (const float*)d_in[13];
    const float* var   = (const float*)d_in[14];
    const float* W3    = (const float*)d_in[15];
    const float* b3    = (const float*)d_in[16];
    const float* W4    = (const float*)d_in[17];
    const float* b4    = (const float*)d_in[18];
    float* out = (float*)d_out;

    k_embproj<<<V_, 256>>>(emb, W1, b1);
    k_main<<<NBLK_, THR_>>>(code, U1, W2, U2, b2,
                            aux, Wlm, blm, gamma, beta, mean, var,
                            W3, b3, W4, b4, out);
}

// round 14
// speedup vs baseline: 1.8396x; 1.8396x over previous
#include <cuda_runtime.h>
#include <cuda_bf16.h>
#include <cstdint>

// ---------------------------------------------------------------------------
// RnnTfModel: k_embproj (exact R1) + fused LSTM/head.
// R14 = R13 resubmit (infra failure; kernel never ran).
// Cross-step pipelined LSTM. Each iteration: ONE merged matvec phase
//   (z2(t): W2.h1_t + U2.h2_{t-1}  AND  z1(t+1): U1.h1_t), then ONE merged
//   combine (h2_t AND h1_{t+1}). 2 barriers/step (was 3). R10 tiling/regs.
// B=512, T=1024, D=H=64, 4H=256, V=8193. 128 blocks x 256 threads.
// ---------------------------------------------------------------------------

#define B_   512
#define T_   1024
#define D_   64
#define G4_  256
#define V_   8193
#define NB_  4
#define NBLK_ 128
#define THR_ 256

using ull = unsigned long long;

__device__ float g_table[V_ * G4_];      // projected embedding table (8.4 MB)

__device__ __forceinline__ void ffma2(ull& d, ull a, ull b) {
    asm("fma.rn.f32x2 %0, %1, %2, %0;" : "+l"(d) : "l"(a), "l"(b));
}
__device__ __forceinline__ float2 unpack2(ull v) {
    float2 f;
    asm("mov.b64 {%0, %1}, %2;" : "=f"(f.x), "=f"(f.y) : "l"(v));
    return f;
}
__device__ __forceinline__ ull pack2(float lo, float hi) {
    ull v;
    asm("mov.b64 %0, {%1, %2};" : "=l"(v) : "f"(lo), "f"(hi));
    return v;
}
__device__ __forceinline__ float sigm_(float x) {
    return 1.0f / (1.0f + __expf(-x));
}
__device__ __forceinline__ float tanh_(float x) {
    float e = __expf(-2.0f * x);
    return (1.0f - e) / (1.0f + e);
}

// ---------------------------------------------------------------------------
// Kernel 1: projected embedding table — EXACT R1 code.
// ---------------------------------------------------------------------------
__global__ void k_embproj(const float* __restrict__ emb,
                          const float* __restrict__ W1,
                          const float* __restrict__ b1) {
    int v = blockIdx.x;
    int j = threadIdx.x;
    __shared__ float e[D_];
    if (j < D_) e[j] = emb[v * D_ + j];
    __syncthreads();
    float acc = b1[j];
#pragma unroll
    for (int k = 0; k < D_; k++) acc += e[k] * __ldg(&W1[k * G4_ + j]);
    g_table[v * G4_ + j] = acc;
}

// ---------------------------------------------------------------------------
// Kernel 2: fused LSTM + head.
// matvec role: thread (kq=j>>6, jq=j&63) -> cols 4jq..4jq+3, k-quarter kq.
// combine role: row r_=j>>6, unit u_=j&63.
// Dynamic smem (floats):
//   [0,    512)   hc1 : [2][4][64] h1 ping-pong
//   [512, 1024)   hc2 : [2][4][64] h2 ping-pong
//   [1024, 5120)  zp1 : [4][4][256] quarter partials z1(t+1)
//   [5120, 9216)  zp2 : [4][4][256] quarter partials z2(t)
//   [9216, 13312) code_s : 4x1024 int
//   [13312,13576) zbn ; [13576,13704) hid
// ---------------------------------------------------------------------------
#define SM_HC1   0
#define SM_HC2   512
#define SM_ZP1   1024
#define SM_ZP2   5120
#define SM_CODE  9216
#define SM_ZBN   13312
#define SM_HID   13576
#define SMEM_BYTES (13704 * 4)

__global__ void __launch_bounds__(THR_, 1)
k_main(const int* __restrict__ code_in,
       const float* __restrict__ U1,
       const float* __restrict__ W2,
       const float* __restrict__ U2,
       const float* __restrict__ b2,
       const float* __restrict__ aux,
       const float* __restrict__ Wlm, const float* __restrict__ blm,
       const float* __restrict__ gamma, const float* __restrict__ beta,
       const float* __restrict__ mean, const float* __restrict__ var,
       const float* __restrict__ W3, const float* __restrict__ b3,
       const float* __restrict__ W4, const float* __restrict__ b4,
       float* __restrict__ out) {
    extern __shared__ __align__(16) float smem[];
    float* hc1   = smem + SM_HC1;
    float* hc2   = smem + SM_HC2;
    float* zp1   = smem + SM_ZP1;
    float* zp2   = smem + SM_ZP2;
    int*   code_s = (int*)(smem + SM_CODE);
    float* zbn   = smem + SM_ZBN;
    float* hid   = smem + SM_HID;

    const int j   = threadIdx.x;
    const int kq  = j >> 6;          // k-quarter (warp-uniform)
    const int jq  = j & 63;
    const int c0  = 4 * jq;
    const int r_  = j >> 6;          // combine row
    const int u_  = j & 63;          // combine unit
    const int b0  = blockIdx.x * NB_;

    // ---- layer-1 weights: U1 rows [16kq,16kq+16) x cols c0..c0+3 ----
    ull w1[4][8];
#pragma unroll
    for (int c = 0; c < 4; c++)
#pragma unroll
        for (int p = 0; p < 8; p++) {
            int k = 16 * kq + 2 * p;
            w1[c][p] = pack2(__ldg(&U1[k * G4_ + c0 + c]),
                             __ldg(&U1[(k + 1) * G4_ + c0 + c]));
        }
    // ---- layer-2 weights: stacked [W2;U2] rows [32kq,32kq+32) ----
    const float* M2 = (kq < 2) ? W2 : U2;
    const int kr0 = 32 * (kq & 1);
    ull w2[4][16];
#pragma unroll
    for (int c = 0; c < 4; c++)
#pragma unroll
        for (int p = 0; p < 16; p++) {
            int k = kr0 + 2 * p;
            w2[c][p] = pack2(__ldg(&M2[k * G4_ + c0 + c]),
                             __ldg(&M2[(k + 1) * G4_ + c0 + c]));
        }

    float4 b2c;
    b2c.x = __ldg(&b2[u_]);
    b2c.y = __ldg(&b2[64 + u_]);
    b2c.z = __ldg(&b2[128 + u_]);
    b2c.w = __ldg(&b2[192 + u_]);

    for (int i = j; i < NB_ * T_; i += THR_) {
        int r = i >> 10, t = i & (T_ - 1);
        code_s[i] = code_in[(b0 + r) * T_ + t];
    }
    hc1[j] = 0.0f; hc1[j + 256] = 0.0f;
    hc2[j] = 0.0f; hc2[j + 256] = 0.0f;
    __syncthreads();   // code_s + zeroed buffers visible

    float c1 = 0.0f, c2 = 0.0f;

    // ---- prologue: h1_0 = f(x_0)  (h1_{-1} = 0, c1_{-1} = 0) ----
    {
        const float* row = &g_table[(size_t)code_s[r_ * T_] * G4_];
        float iv = sigm_(__ldg(&row[u_]));
        float gv = tanh_(__ldg(&row[128 + u_]));
        float ov = sigm_(__ldg(&row[192 + u_]));
        c1 = iv * gv;
        hc1[0 * 256 + r_ * 64 + u_] = ov * tanh_(c1);  // buf1[0] = h1_0
    }
    // cur = x_1 (used by combine(0) for h1_1)
    float4 cur;
    {
        const float* row = &g_table[(size_t)code_s[r_ * T_ + 1] * G4_];
        cur.x = __ldg(&row[u_]);
        cur.y = __ldg(&row[64 + u_]);
        cur.z = __ldg(&row[128 + u_]);
        cur.w = __ldg(&row[192 + u_]);
    }
    __syncthreads();   // h1_0 visible

    // ============================ LSTM loop ================================
    for (int t = 0; t < T_; t++) {
        const int ca = t & 1, cb = (t + 1) & 1;

        // prefetch x_{t+2} (clamped)
        float4 nxt;
        {
            int tn = (t + 2 < T_) ? (t + 2) : (T_ - 1);
            const float* row = &g_table[(size_t)code_s[r_ * T_ + tn] * G4_];
            nxt.x = __ldg(&row[u_]);
            nxt.y = __ldg(&row[64 + u_]);
            nxt.z = __ldg(&row[128 + u_]);
            nxt.w = __ldg(&row[192 + u_]);
        }

        const float* h1b = &hc1[ca * 256];   // h1_t
        const float* h2b = &hc2[cb * 256];   // h2_{t-1}
        const float* kb  = (kq < 2) ? h1b : h2b;

        // ---- z2(t) partials: 32 stacked k-rows ----
#pragma unroll
        for (int pass = 0; pass < 2; pass++) {
            ull acc[2][4] = {{0, 0, 0, 0}, {0, 0, 0, 0}};
#pragma unroll
            for (int i = 0; i < 8; i++) {
#pragma unroll
                for (int rr = 0; rr < 2; rr++) {
                    int r = 2 * pass + rr;
                    ulonglong2 hv = *(const ulonglong2*)
                        &kb[r * 64 + kr0 + 4 * i];
#pragma unroll
                    for (int c = 0; c < 4; c++) {
                        ffma2(acc[rr][c], hv.x, w2[c][2 * i]);
                        ffma2(acc[rr][c], hv.y, w2[c][2 * i + 1]);
                    }
                }
            }
#pragma unroll
            for (int rr = 0; rr < 2; rr++) {
                int r = 2 * pass + rr;
                float2 p0 = unpack2(acc[rr][0]), p1 = unpack2(acc[rr][1]);
                float2 p2 = unpack2(acc[rr][2]), p3 = unpack2(acc[rr][3]);
                *(float4*)&zp2[kq * 1024 + r * G4_ + c0] =
                    make_float4(p0.x + p0.y, p1.x + p1.y,
                                p2.x + p2.y, p3.x + p3.y);
            }
        }
        // ---- z1(t+1) partials: 16 k-rows of U1 against h1_t ----
#pragma unroll
        for (int pass = 0; pass < 2; pass++) {
            ull acc[2][4] = {{0, 0, 0, 0}, {0, 0, 0, 0}};
#pragma unroll
            for (int i = 0; i < 4; i++) {
#pragma unroll
                for (int rr = 0; rr < 2; rr++) {
                    int r = 2 * pass + rr;
                    ulonglong2 hv = *(const ulonglong2*)
                        &h1b[r * 64 + 16 * kq + 4 * i];
#pragma unroll
                    for (int c = 0; c < 4; c++) {
                        ffma2(acc[rr][c], hv.x, w1[c][2 * i]);
                        ffma2(acc[rr][c], hv.y, w1[c][2 * i + 1]);
                    }
                }
            }
#pragma unroll
            for (int rr = 0; rr < 2; rr++) {
                int r = 2 * pass + rr;
                float2 p0 = unpack2(acc[rr][0]), p1 = unpack2(acc[rr][1]);
                float2 p2 = unpack2(acc[rr][2]), p3 = unpack2(acc[rr][3]);
                *(float4*)&zp1[kq * 1024 + r * G4_ + c0] =
                    make_float4(p0.x + p0.y, p1.x + p1.y,
                                p2.x + p2.y, p3.x + p3.y);
            }
        }
        __syncthreads();   // S_a: zp1, zp2 ready

        // ---- merged combine: h2_t and h1_{t+1} ----
        {
            float z0 = b2c.x, z1g = b2c.y, z2g = b2c.z, z3 = b2c.w;
            float y0 = cur.x, y1 = cur.y, y2 = cur.z, y3 = cur.w;
#pragma unroll
            for (int q = 0; q < 4; q++) {
                z0  += zp2[q * 1024 + r_ * G4_ + u_];
                z1g += zp2[q * 1024 + r_ * G4_ + 64 + u_];
                z2g += zp2[q * 1024 + r_ * G4_ + 128 + u_];
                z3  += zp2[q * 1024 + r_ * G4_ + 192 + u_];
                y0  += zp1[q * 1024 + r_ * G4_ + u_];
                y1  += zp1[q * 1024 + r_ * G4_ + 64 + u_];
                y2  += zp1[q * 1024 + r_ * G4_ + 128 + u_];
                y3  += zp1[q * 1024 + r_ * G4_ + 192 + u_];
            }
            // layer 2: h2_t
            float iv2 = sigm_(z0), fv2 = sigm_(z1g);
            float gv2 = tanh_(z2g), ov2 = sigm_(z3);
            c2 = fv2 * c2 + iv2 * gv2;
            hc2[ca * 256 + r_ * 64 + u_] = ov2 * tanh_(c2);
            // layer 1: h1_{t+1}
            float iv1 = sigm_(y0), fv1 = sigm_(y1);
            float gv1 = tanh_(y2), ov1 = sigm_(y3);
            c1 = fv1 * c1 + iv1 * gv1;
            hc1[cb * 256 + r_ * 64 + u_] = ov1 * tanh_(c1);
        }
        __syncthreads();   // S_b: new h states visible

        cur = nxt;
    }

    // final h2 = hc2[(T_-1)&1] = hc2[1]
    // ============================ head (4 rows) ============================
    if (j < 264) {
        int r = j / 66, k = j % 66;
        float v = (k < 2) ? aux[(b0 + r) * 2 + k]
                          : hc2[1 * 256 + r * 64 + (k - 2)];
        zbn[r * 66 + k] =
            gamma[k] * (v - mean[k]) * rsqrtf(var[k] + 1e-3f) + beta[k];
    }
    __syncthreads();
    if (j < 128) {
        int r = j >> 5, i = j & 31;
        float acc = b3[i];
#pragma unroll
        for (int k = 0; k < 66; k++)
            acc += zbn[r * 66 + k] * __ldg(&W3[k * 32 + i]);
        hid[r * 32 + i] = fmaxf(acc, 0.0f);
    }
    __syncthreads();
    if (j < NB_) {
        int r = j;
        float o0 = b4[0], o1 = b4[1];
#pragma unroll
        for (int k = 0; k < 32; k++) {
            o0 += hid[r * 32 + k] * __ldg(&W4[k * 2 + 0]);
            o1 += hid[r * 32 + k] * __ldg(&W4[k * 2 + 1]);
        }
        float m = fmaxf(o0, o1);
        float e0 = __expf(o0 - m), e1 = __expf(o1 - m);
        float inv = 1.0f / (e0 + e1);
        out[(b0 + r) * 2 + 0] = e0 * inv;
        out[(b0 + r) * 2 + 1] = e1 * inv;

        float l0 = blm[0], l1 = blm[1];
#pragma unroll
        for (int k = 0; k < 64; k++) {
            float h = hc2[1 * 256 + r * 64 + k];
            l0 += h * __ldg(&Wlm[k * 2 + 0]);
            l1 += h * __ldg(&Wlm[k * 2 + 1]);
        }
        out[B_ * 2 + (b0 + r) * 2 + 0] = sigm_(l0);
        out[B_ * 2 + (b0 + r) * 2 + 1] = sigm_(l1);
    }
}

// ---------------------------------------------------------------------------
// launcher
// inputs: 0 aux_in, 1 code_in, 2 emb, 3 W1, 4 U1, 5 b1, 6 W2, 7 U2, 8 b2,
//         9 Wlm, 10 blm, 11 bn_gamma, 12 bn_beta, 13 bn_mean, 14 bn_var,
//         15 W3, 16 b3, 17 W4, 18 b4
// ---------------------------------------------------------------------------
extern "C" void kernel_launch(void* const* d_in, const int* in_sizes, int n_in,
                              void* d_out, int out_size) {
    const float* aux   = (const float*)d_in[0];
    const int*   code  = (const int*)d_in[1];
    const float* emb   = (const float*)d_in[2];
    const float* W1    = (const float*)d_in[3];
    const float* U1    = (const float*)d_in[4];
    const float* b1    = (const float*)d_in[5];
    const float* W2    = (const float*)d_in[6];
    const float* U2    = (const float*)d_in[7];
    const float* b2    = (const float*)d_in[8];
    const float* Wlm   = (const float*)d_in[9];
    const float* blm   = (const float*)d_in[10];
    const float* gamma = (const float*)d_in[11];
    const float* beta  = (const float*)d_in[12];
    const float* mean  = (const float*)d_in[13];
    const float* var   = (const float*)d_in[14];
    const float* W3    = (const float*)d_in[15];
    const float* b3    = (const float*)d_in[16];
    const float* W4    = (const float*)d_in[17];
    const float* b4    = (const float*)d_in[18];
    float* out = (float*)d_out;

    cudaFuncSetAttribute(k_main, cudaFuncAttributeMaxDynamicSharedMemorySize,
                         SMEM_BYTES);

    k_embproj<<<V_, 256>>>(emb, W1, b1);
    k_main<<<NBLK_, THR_, SMEM_BYTES>>>(code, U1, W2, U2, b2,
                                        aux, Wlm, blm, gamma, beta, mean, var,
                                        W3, b3, W4, b4, out);
}

// round 15
// speedup vs baseline: 1.8986x; 1.0321x over previous
#include <cuda_runtime.h>
#include <cuda_bf16.h>
#include <cstdint>

// ---------------------------------------------------------------------------
// RnnTfModel: k_embproj (exact R1) + fused LSTM/head.
// R15: 512 threads (4 warps/SMSP). Thread (ke = k-eighth, jq) owns 4 cols x
//   k-eighth: per-thread FMA and broadcast-LDS halved, block totals constant.
//   Combine split by layer across thread halves. 2 barriers/step.
// B=512, T=1024, D=H=64, 4H=256, V=8193. 128 blocks x 512 threads.
// ---------------------------------------------------------------------------

#define B_   512
#define T_   1024
#define D_   64
#define G4_  256
#define V_   8193
#define NB_  4
#define NBLK_ 128
#define THR_ 512

using ull = unsigned long long;

__device__ float g_table[V_ * G4_];      // projected embedding table (8.4 MB)

__device__ __forceinline__ void ffma2(ull& d, ull a, ull b) {
    asm("fma.rn.f32x2 %0, %1, %2, %0;" : "+l"(d) : "l"(a), "l"(b));
}
__device__ __forceinline__ float2 unpack2(ull v) {
    float2 f;
    asm("mov.b64 {%0, %1}, %2;" : "=f"(f.x), "=f"(f.y) : "l"(v));
    return f;
}
__device__ __forceinline__ ull pack2(float lo, float hi) {
    ull v;
    asm("mov.b64 %0, {%1, %2};" : "=l"(v) : "f"(lo), "f"(hi));
    return v;
}
__device__ __forceinline__ float sigm_(float x) {
    return 1.0f / (1.0f + __expf(-x));
}
__device__ __forceinline__ float tanh_(float x) {
    float e = __expf(-2.0f * x);
    return (1.0f - e) / (1.0f + e);
}

// ---------------------------------------------------------------------------
// Kernel 1: projected embedding table — EXACT R1 code.
// ---------------------------------------------------------------------------
__global__ void k_embproj(const float* __restrict__ emb,
                          const float* __restrict__ W1,
                          const float* __restrict__ b1) {
    int v = blockIdx.x;
    int j = threadIdx.x;
    __shared__ float e[D_];
    if (j < D_) e[j] = emb[v * D_ + j];
    __syncthreads();
    float acc = b1[j];
#pragma unroll
    for (int k = 0; k < D_; k++) acc += e[k] * __ldg(&W1[k * G4_ + j]);
    g_table[v * G4_ + j] = acc;
}

// ---------------------------------------------------------------------------
// Kernel 2: fused LSTM + head, 512 threads.
// matvec role: thread (ke = j>>6 in [0,8), jq = j&63) -> cols 4jq..4jq+3.
//   z2: stacked [h1_t; h2_{t-1}] rows [16ke, 16ke+16).
//   z1: U1 rows [8ke, 8ke+8) vs h1_t.
// combine role: lay = j>>8 (0: h2_t, 1: h1_{t+1}), rc=(j>>6)&3, uc=j&63.
// Dynamic smem (floats):
//   [0,512) hc1[2][4][64]; [512,1024) hc2[2][4][64];
//   [1024,9216) zp1[8][4][256]; [9216,17408) zp2[8][4][256];
//   [17408,21504) code_s; [21504,21768) zbn; [21768,21896) hid
// ---------------------------------------------------------------------------
#define SM_HC1   0
#define SM_HC2   512
#define SM_ZP1   1024
#define SM_ZP2   9216
#define SM_CODE  17408
#define SM_ZBN   21504
#define SM_HID   21768
#define SMEM_BYTES (21896 * 4)

__global__ void __launch_bounds__(THR_, 1)
k_main(const int* __restrict__ code_in,
       const float* __restrict__ U1,
       const float* __restrict__ W2,
       const float* __restrict__ U2,
       const float* __restrict__ b2,
       const float* __restrict__ aux,
       const float* __restrict__ Wlm, const float* __restrict__ blm,
       const float* __restrict__ gamma, const float* __restrict__ beta,
       const float* __restrict__ mean, const float* __restrict__ var,
       const float* __restrict__ W3, const float* __restrict__ b3,
       const float* __restrict__ W4, const float* __restrict__ b4,
       float* __restrict__ out) {
    extern __shared__ __align__(16) float smem[];
    float* hc1   = smem + SM_HC1;
    float* hc2   = smem + SM_HC2;
    float* zp1   = smem + SM_ZP1;
    float* zp2   = smem + SM_ZP2;
    int*   code_s = (int*)(smem + SM_CODE);
    float* zbn   = smem + SM_ZBN;
    float* hid   = smem + SM_HID;

    const int j   = threadIdx.x;
    const int ke  = j >> 6;          // k-eighth (warp-uniform)
    const int jq  = j & 63;
    const int c0  = 4 * jq;
    const int lay = j >> 8;          // combine layer: 0 -> h2, 1 -> h1
    const int rc  = (j >> 6) & 3;    // combine row
    const int uc  = j & 63;          // combine unit
    const int b0  = blockIdx.x * NB_;

    // ---- z2 weights: stacked [W2;U2] rows [16ke,16ke+16) x cols c0..c0+3 ----
    const float* M2 = (ke < 4) ? W2 : U2;
    const int kr0 = 16 * (ke & 3);
    ull w2[4][8];
#pragma unroll
    for (int c = 0; c < 4; c++)
#pragma unroll
        for (int p = 0; p < 8; p++) {
            int k = kr0 + 2 * p;
            w2[c][p] = pack2(__ldg(&M2[k * G4_ + c0 + c]),
                             __ldg(&M2[(k + 1) * G4_ + c0 + c]));
        }
    // ---- z1 weights: U1 rows [8ke,8ke+8) x cols c0..c0+3 ----
    ull w1[4][4];
#pragma unroll
    for (int c = 0; c < 4; c++)
#pragma unroll
        for (int p = 0; p < 4; p++) {
            int k = 8 * ke + 2 * p;
            w1[c][p] = pack2(__ldg(&U1[k * G4_ + c0 + c]),
                             __ldg(&U1[(k + 1) * G4_ + c0 + c]));
        }

    // combine-role constants
    float4 b2c = make_float4(0.f, 0.f, 0.f, 0.f);
    if (lay == 0) {
        b2c.x = __ldg(&b2[uc]);
        b2c.y = __ldg(&b2[64 + uc]);
        b2c.z = __ldg(&b2[128 + uc]);
        b2c.w = __ldg(&b2[192 + uc]);
    }

    for (int i = j; i < NB_ * T_; i += THR_) {
        int r = i >> 10, t = i & (T_ - 1);
        code_s[i] = code_in[(b0 + r) * T_ + t];
    }
    hc1[j] = 0.0f;                      // j in [0,512) covers both buffers
    hc2[j] = 0.0f;
    __syncthreads();

    float c1 = 0.0f, c2 = 0.0f;
    float4 cur = make_float4(0.f, 0.f, 0.f, 0.f);

    // ---- prologue (lay==1 threads): h1_0 = f(x_0), c1 init; cur = x_1 ----
    if (lay == 1) {
        const float* row0 = &g_table[(size_t)code_s[rc * T_] * G4_];
        float iv = sigm_(__ldg(&row0[uc]));
        float gv = tanh_(__ldg(&row0[128 + uc]));
        float ov = sigm_(__ldg(&row0[192 + uc]));
        c1 = iv * gv;
        hc1[0 * 256 + rc * 64 + uc] = ov * tanh_(c1);   // buf1[0] = h1_0
        const float* row1 = &g_table[(size_t)code_s[rc * T_ + 1] * G4_];
        cur.x = __ldg(&row1[uc]);
        cur.y = __ldg(&row1[64 + uc]);
        cur.z = __ldg(&row1[128 + uc]);
        cur.w = __ldg(&row1[192 + uc]);
    }
    __syncthreads();   // h1_0 visible

    // ============================ LSTM loop ================================
    for (int t = 0; t < T_; t++) {
        const int ca = t & 1, cb = (t + 1) & 1;

        float4 nxt = make_float4(0.f, 0.f, 0.f, 0.f);
        if (lay == 1) {                  // prefetch x_{t+2} (clamped)
            int tn = (t + 2 < T_) ? (t + 2) : (T_ - 1);
            const float* row = &g_table[(size_t)code_s[rc * T_ + tn] * G4_];
            nxt.x = __ldg(&row[uc]);
            nxt.y = __ldg(&row[64 + uc]);
            nxt.z = __ldg(&row[128 + uc]);
            nxt.w = __ldg(&row[192 + uc]);
        }

        const float* h1b = &hc1[ca * 256];   // h1_t
        const float* h2b = &hc2[cb * 256];   // h2_{t-1}
        const float* kb  = (ke < 4) ? h1b : h2b;

        // ---- z2(t) partials: this thread's 16 stacked k-rows ----
#pragma unroll
        for (int r = 0; r < NB_; r++) {
            ull acc[4] = {0, 0, 0, 0};
#pragma unroll
            for (int i = 0; i < 4; i++) {
                ulonglong2 hv = *(const ulonglong2*)&kb[r * 64 + kr0 + 4 * i];
#pragma unroll
                for (int c = 0; c < 4; c++) {
                    ffma2(acc[c], hv.x, w2[c][2 * i]);
                    ffma2(acc[c], hv.y, w2[c][2 * i + 1]);
                }
            }
            float2 p0 = unpack2(acc[0]), p1 = unpack2(acc[1]);
            float2 p2 = unpack2(acc[2]), p3 = unpack2(acc[3]);
            *(float4*)&zp2[ke * 1024 + r * G4_ + c0] =
                make_float4(p0.x + p0.y, p1.x + p1.y,
                            p2.x + p2.y, p3.x + p3.y);
        }
        // ---- z1(t+1) partials: this thread's 8 U1 k-rows vs h1_t ----
#pragma unroll
        for (int r = 0; r < NB_; r++) {
            ull acc[4] = {0, 0, 0, 0};
#pragma unroll
            for (int i = 0; i < 2; i++) {
                ulonglong2 hv = *(const ulonglong2*)
                    &h1b[r * 64 + 8 * ke + 4 * i];
#pragma unroll
                for (int c = 0; c < 4; c++) {
                    ffma2(acc[c], hv.x, w1[c][2 * i]);
                    ffma2(acc[c], hv.y, w1[c][2 * i + 1]);
                }
            }
            float2 p0 = unpack2(acc[0]), p1 = unpack2(acc[1]);
            float2 p2 = unpack2(acc[2]), p3 = unpack2(acc[3]);
            *(float4*)&zp1[ke * 1024 + r * G4_ + c0] =
                make_float4(p0.x + p0.y, p1.x + p1.y,
                            p2.x + p2.y, p3.x + p3.y);
        }
        __syncthreads();   // S_a: zp1, zp2 ready

        // ---- combine, split by layer across thread halves ----
        if (lay == 0) {
            // h2_t for (rc, uc)
            float z0 = b2c.x, z1g = b2c.y, z2g = b2c.z, z3 = b2c.w;
#pragma unroll
            for (int q = 0; q < 8; q++) {
                z0  += zp2[q * 1024 + rc * G4_ + uc];
                z1g += zp2[q * 1024 + rc * G4_ + 64 + uc];
                z2g += zp2[q * 1024 + rc * G4_ + 128 + uc];
                z3  += zp2[q * 1024 + rc * G4_ + 192 + uc];
            }
            float iv = sigm_(z0), fv = sigm_(z1g);
            float gv = tanh_(z2g), ov = sigm_(z3);
            c2 = fv * c2 + iv * gv;
            hc2[ca * 256 + rc * 64 + uc] = ov * tanh_(c2);
        } else {
            // h1_{t+1} for (rc, uc)
            float y0 = cur.x, y1 = cur.y, y2 = cur.z, y3 = cur.w;
#pragma unroll
            for (int q = 0; q < 8; q++) {
                y0 += zp1[q * 1024 + rc * G4_ + uc];
                y1 += zp1[q * 1024 + rc * G4_ + 64 + uc];
                y2 += zp1[q * 1024 + rc * G4_ + 128 + uc];
                y3 += zp1[q * 1024 + rc * G4_ + 192 + uc];
            }
            float iv = sigm_(y0), fv = sigm_(y1);
            float gv = tanh_(y2), ov = sigm_(y3);
            c1 = fv * c1 + iv * gv;
            hc1[cb * 256 + rc * 64 + uc] = ov * tanh_(c1);
            cur = nxt;
        }
        __syncthreads();   // S_b: new h states visible
    }

    // final h2 = hc2[1]  (last write: t=1023, ca=1)
    // ============================ head (4 rows) ============================
    if (j < 264) {
        int r = j / 66, k = j % 66;
        float v = (k < 2) ? aux[(b0 + r) * 2 + k]
                          : hc2[1 * 256 + r * 64 + (k - 2)];
        zbn[r * 66 + k] =
            gamma[k] * (v - mean[k]) * rsqrtf(var[k] + 1e-3f) + beta[k];
    }
    __syncthreads();
    if (j < 128) {
        int r = j >> 5, i = j & 31;
        float acc = b3[i];
#pragma unroll
        for (int k = 0; k < 66; k++)
            acc += zbn[r * 66 + k] * __ldg(&W3[k * 32 + i]);
        hid[r * 32 + i] = fmaxf(acc, 0.0f);
    }
    __syncthreads();
    if (j < NB_) {
        int r = j;
        float o0 = b4[0], o1 = b4[1];
#pragma unroll
        for (int k = 0; k < 32; k++) {
            o0 += hid[r * 32 + k] * __ldg(&W4[k * 2 + 0]);
            o1 += hid[r * 32 + k] * __ldg(&W4[k * 2 + 1]);
        }
        float m = fmaxf(o0, o1);
        float e0 = __expf(o0 - m), e1 = __expf(o1 - m);
        float inv = 1.0f / (e0 + e1);
        out[(b0 + r) * 2 + 0] = e0 * inv;
        out[(b0 + r) * 2 + 1] = e1 * inv;

        float l0 = blm[0], l1 = blm[1];
#pragma unroll
        for (int k = 0; k < 64; k++) {
            float h = hc2[1 * 256 + r * 64 + k];
            l0 += h * __ldg(&Wlm[k * 2 + 0]);
            l1 += h * __ldg(&Wlm[k * 2 + 1]);
        }
        out[B_ * 2 + (b0 + r) * 2 + 0] = sigm_(l0);
        out[B_ * 2 + (b0 + r) * 2 + 1] = sigm_(l1);
    }
}

// ---------------------------------------------------------------------------
// launcher
// inputs: 0 aux_in, 1 code_in, 2 emb, 3 W1, 4 U1, 5 b1, 6 W2, 7 U2, 8 b2,
//         9 Wlm, 10 blm, 11 bn_gamma, 12 bn_beta, 13 bn_mean, 14 bn_var,
//         15 W3, 16 b3, 17 W4, 18 b4
// ---------------------------------------------------------------------------
extern "C" void kernel_launch(void* const* d_in, const int* in_sizes, int n_in,
                              void* d_out, int out_size) {
    const float* aux   = (const float*)d_in[0];
    const int*   code  = (const int*)d_in[1];
    const float* emb   = (const float*)d_in[2];
    const float* W1    = (const float*)d_in[3];
    const float* U1    = (const float*)d_in[4];
    const float* b1    = (const float*)d_in[5];
    const float* W2    = (const float*)d_in[6];
    const float* U2    = (const float*)d_in[7];
    const float* b2    = (const float*)d_in[8];
    const float* Wlm   = (const float*)d_in[9];
    const float* blm   = (const float*)d_in[10];
    const float* gamma = (const float*)d_in[11];
    const float* beta  = (const float*)d_in[12];
    const float* mean  = (const float*)d_in[13];
    const float* var   = (const float*)d_in[14];
    const float* W3    = (const float*)d_in[15];
    const float* b3    = (const float*)d_in[16];
    const float* W4    = (const float*)d_in[17];
    const float* b4    = (const float*)d_in[18];
    float* out = (float*)d_out;

    cudaFuncSetAttribute(k_main, cudaFuncAttributeMaxDynamicSharedMemorySize,
                         SMEM_BYTES);

    k_embproj<<<V_, 256>>>(emb, W1, b1);
    k_main<<<NBLK_, THR_, SMEM_BYTES>>>(code, U1, W2, U2, b2,
                                        aux, Wlm, blm, gamma, beta, mean, var,
                                        W3, b3, W4, b4, out);
}